// round 2
// baseline (speedup 1.0000x reference)
#include <cuda_runtime.h>
#include <math.h>
#include <stdint.h>

#define THREADS 512
#define M 8192            // packed complex FFT size
#define NFULL 16384       // real signal length
#define NBINS 8193        // rfft bins
#define ROWS 512
#define PI_D 3.14159265358979323846

// ---------------- global scratch / accumulators (no allocation allowed) ---------
__device__ double g_pear;
__device__ double g_cos;
__device__ double g_absdiff;
__device__ double g_tp;
__device__ double g_nmi;

__device__ float2 g_W2048[2048];    // e^{-2pi i k/8192}, k<2048 (rest by symmetry)
__device__ float2 g_WN[NBINS];      // e^{-i pi k/8192},  k=0..8192

// ---------------- complex helpers ----------------
__device__ __forceinline__ float2 cmul(float2 a, float2 b){
    return make_float2(a.x*b.x - a.y*b.y, a.x*b.y + a.y*b.x);
}
__device__ __forceinline__ float2 cconj(float2 a){ return make_float2(a.x, -a.y); }

__device__ __forceinline__ float warp_sum(float v){
    #pragma unroll
    for (int o = 16; o; o >>= 1) v += __shfl_down_sync(0xffffffffu, v, o);
    return v;
}

// ---------------- init kernels ----------------
__global__ void zero_acc_kernel(){
    g_pear = 0.0; g_cos = 0.0; g_absdiff = 0.0; g_tp = 0.0; g_nmi = 0.0;
}

__global__ void init_tw_kernel(){
    int k = blockIdx.x * blockDim.x + threadIdx.x;
    if (k < 2048){
        double a = -2.0 * PI_D * (double)k / 8192.0;
        g_W2048[k] = make_float2((float)cos(a), (float)sin(a));
    }
    if (k < NBINS){
        double a = -PI_D * (double)k / 8192.0;
        g_WN[k] = make_float2((float)cos(a), (float)sin(a));
    }
}

// ---------------- in-smem radix-2 FFT, size 8192, DIT, bit-reversed input ------
__device__ void fft8192(float2* Z, const float2* W, bool inverse){
    #pragma unroll 1
    for (int s = 1; s <= 13; s++){
        int half = 1 << (s - 1);
        int sh = 13 - s;
        #pragma unroll 1
        for (int j = threadIdx.x; j < 4096; j += THREADS){
            int t  = j & (half - 1);
            int i1 = ((j >> (s - 1)) << s) + t;
            int i2 = i1 + half;
            int k  = t << sh;                  // twiddle index in [0,4096)
            float2 w;
            if (k < 2048) w = W[k];
            else { float2 ww = W[k - 2048]; w = make_float2(ww.y, -ww.x); } // * e^{-i pi/2}
            if (inverse) w.y = -w.y;
            float2 u = Z[i1];
            float2 v = cmul(Z[i2], w);
            Z[i1] = make_float2(u.x + v.x, u.y + v.y);
            Z[i2] = make_float2(u.x - v.x, u.y - v.y);
        }
        __syncthreads();
    }
}

// Unpack: X[k] of the length-16384 real signal from packed Z (= FFT8192 of even+i*odd).
// w must be e^{-i pi k/8192}; valid for k in [0, 8192].
__device__ __forceinline__ float2 spec_at(const float2* Z, int k, float2 w){
    float2 a = Z[k & (M - 1)];
    float2 b = Z[(M - k) & (M - 1)];
    float2 E = make_float2(0.5f*(a.x + b.x),  0.5f*(a.y - b.y));
    float2 O = make_float2(0.5f*(a.y + b.y), -0.5f*(a.x - b.x));
    float2 WO = cmul(w, O);
    return make_float2(E.x + WO.x, E.y + WO.y);
}

// ---------------- main fused kernel: one CTA per row ----------------
__global__ __launch_bounds__(THREADS, 1)
void row_kernel(const float* __restrict__ pred, const float* __restrict__ targ,
                const int* __restrict__ pi){
    extern __shared__ float2 sm[];
    float2* Zp = sm;                    // 8192
    float2* Zt = sm + M;                // 8192
    float2* Cb = sm + 2*M;              // 8193
    float2* Wt = sm + 2*M + NBINS;      // 2048

    __shared__ float s_red[16][6];
    __shared__ int   s_idx[16];

    const int tid  = threadIdx.x;
    const int warp = tid >> 5, lane = tid & 31;
    const int row  = blockIdx.x;
    const int i0   = *pi;

    const float2* xr = (const float2*)(pred + ((size_t)i0 * ROWS + row) * (size_t)NFULL);
    const float2* yr = (const float2*)(targ + (size_t)row * (size_t)NFULL);

    // twiddle table -> smem
    #pragma unroll 1
    for (int k = tid; k < 2048; k += THREADS) Wt[k] = g_W2048[k];

    // ---- load (bit-reversed pack) + per-row Pearson moments ----
    float sx = 0.f, sy = 0.f, sxy = 0.f, sx2 = 0.f, sy2 = 0.f;
    #pragma unroll 1
    for (int n = tid; n < M; n += THREADS){
        float2 a = xr[n], b = yr[n];
        sx  += a.x + a.y;          sy  += b.x + b.y;
        sxy += a.x*b.x + a.y*b.y;
        sx2 += a.x*a.x + a.y*a.y;  sy2 += b.x*b.x + b.y*b.y;
        int r = __brev(n) >> 19;   // 13-bit reversal
        Zp[r] = a; Zt[r] = b;
    }
    sx  = warp_sum(sx);  sy  = warp_sum(sy); sxy = warp_sum(sxy);
    sx2 = warp_sum(sx2); sy2 = warp_sum(sy2);
    if (lane == 0){
        s_red[warp][0]=sx; s_red[warp][1]=sy; s_red[warp][2]=sxy;
        s_red[warp][3]=sx2; s_red[warp][4]=sy2;
    }
    __syncthreads();
    if (tid == 0){
        double Sx=0,Sy=0,Sxy=0,Sx2=0,Sy2=0;
        for (int w = 0; w < 16; w++){
            Sx+=s_red[w][0]; Sy+=s_red[w][1]; Sxy+=s_red[w][2];
            Sx2+=s_red[w][3]; Sy2+=s_red[w][4];
        }
        const double N = (double)NFULL;
        double pear = (N*Sxy - Sx*Sy) / sqrt((N*Sx2 - Sx*Sx) * (N*Sy2 - Sy*Sy));
        atomicAdd(&g_pear, 1.0 - pear);
    }
    __syncthreads();

    // ---- forward FFTs (unnormalized DFT == jnp.fft.rfft convention) ----
    fft8192(Zp, Wt, false);
    fft8192(Zt, Wt, false);

    // ---- spectra: power-spectrum sums + hann-windowed phase correlation ----
    float accd = 0.f, acct = 0.f;
    #pragma unroll 1
    for (int k = tid; k <= 8192; k += THREADS){
        float2 w0 = g_WN[k];
        float2 X0p = spec_at(Zp, k, w0);
        float2 X0t = spec_at(Zt, k, w0);
        float2 Xmp, Xmt, Xpp, Xpt;
        if (k == 0){
            float2 w1 = g_WN[1];
            Xmp = cconj(spec_at(Zp, 1, w1));    // X[-1] = conj(X[1])
            Xmt = cconj(spec_at(Zt, 1, w1));
        } else {
            float2 wm = g_WN[k-1];
            Xmp = spec_at(Zp, k-1, wm);
            Xmt = spec_at(Zt, k-1, wm);
        }
        if (k == 8192){
            float2 w1 = g_WN[8191];
            Xpp = cconj(spec_at(Zp, 8191, w1)); // X[8193] = conj(X[8191])
            Xpt = cconj(spec_at(Zt, 8191, w1));
        } else {
            float2 wp = g_WN[k+1];
            Xpp = spec_at(Zp, k+1, wp);
            Xpt = spec_at(Zt, k+1, wp);
        }
        // power spectrum (un-windowed)
        float pp = X0p.x*X0p.x + X0p.y*X0p.y;
        float pt = X0t.x*X0t.x + X0t.y*X0t.y;
        accd += fabsf(pp - pt);
        acct += pt;
        // hann window in frequency: 0.5*X[k] - 0.25*(X[k-1]+X[k+1])
        float2 xf = make_float2(0.5f*X0p.x - 0.25f*(Xmp.x + Xpp.x),
                                0.5f*X0p.y - 0.25f*(Xmp.y + Xpp.y));
        float2 tf = make_float2(0.5f*X0t.x - 0.25f*(Xmt.x + Xpt.x),
                                0.5f*X0t.y - 0.25f*(Xmt.y + Xpt.y));
        float2 c = cmul(xf, cconj(tf));
        float inv = rsqrtf(c.x*c.x + c.y*c.y);
        Cb[k] = make_float2(c.x*inv, c.y*inv);   // phase-only correlation
    }
    accd = warp_sum(accd); acct = warp_sum(acct);
    if (lane == 0){ s_red[warp][0] = accd; s_red[warp][1] = acct; }
    __syncthreads();
    if (tid == 0){
        double d = 0.0, t2 = 0.0;
        for (int w = 0; w < 16; w++){ d += s_red[w][0]; t2 += s_red[w][1]; }
        atomicAdd(&g_absdiff, d);
        atomicAdd(&g_tp, t2);
    }
    __syncthreads();

    // ---- pack spectrum back for real inverse FFT (into Zp, bit-reversed) ----
    #pragma unroll 1
    for (int k = tid; k < M; k += THREADS){
        float2 Ck  = Cb[k];
        float2 Ck2 = (k == 0) ? Cb[8192] : cconj(Cb[8192 - k]);  // C[k+8192]
        float2 E = make_float2(0.5f*(Ck.x + Ck2.x), 0.5f*(Ck.y + Ck2.y));
        float2 D = make_float2(0.5f*(Ck.x - Ck2.x), 0.5f*(Ck.y - Ck2.y));
        float2 wn = cconj(g_WN[k]);             // e^{+i pi k/8192}
        float2 O  = cmul(wn, D);
        Zp[__brev(k) >> 19] = make_float2(E.x - O.y, E.y + O.x);  // E + i*O
    }
    __syncthreads();
    fft8192(Zp, Wt, true);   // unnormalized IDFT; positive scale -> argmax invariant

    // ---- argmax over 16384 real samples (first-occurrence tie break) ----
    float best = -INFINITY; int bi = 0x7fffffff;
    #pragma unroll 1
    for (int n = tid; n < M; n += THREADS){
        float2 z = Zp[n];                 // y[2n] = Re, y[2n+1] = Im
        int e = 2*n, o = 2*n + 1;
        if (z.x > best || (z.x == best && e < bi)){ best = z.x; bi = e; }
        if (z.y > best || (z.y == best && o < bi)){ best = z.y; bi = o; }
    }
    #pragma unroll
    for (int off = 16; off; off >>= 1){
        float ov = __shfl_down_sync(0xffffffffu, best, off);
        int   oi = __shfl_down_sync(0xffffffffu, bi,   off);
        if (ov > best || (ov == best && oi < bi)){ best = ov; bi = oi; }
    }
    if (lane == 0){ s_red[warp][0] = best; s_idx[warp] = bi; }
    __syncthreads();
    if (tid == 0){
        best = s_red[0][0]; bi = s_idx[0];
        for (int w = 1; w < 16; w++){
            float v = s_red[w][0]; int ix = s_idx[w];
            if (v > best || (v == best && ix < bi)){ best = v; bi = ix; }
        }
        atomicAdd(&g_cos, (double)cosf(2.0f * (float)PI_D * (float)bi / 16384.0f));
    }
}

// ---------------- mutual information kernel: one CTA per row ----------------
__global__ __launch_bounds__(THREADS)
void mi_kernel(const float* __restrict__ pred, const float* __restrict__ targ,
               const int* __restrict__ pi){
    __shared__ float s_red[16][4];
    __shared__ float s_mm[4];            // xmin,xmax,ymin,ymax
    __shared__ unsigned hist[100];

    const int tid = threadIdx.x;
    const int warp = tid >> 5, lane = tid & 31;
    const int row = blockIdx.x;
    const int i0 = *pi;
    const float* x = pred + ((size_t)i0 * ROWS + row) * (size_t)NFULL;
    const float* y = targ + (size_t)row * (size_t)NFULL;

    if (tid < 100) hist[tid] = 0u;

    float xmn = INFINITY, xmx = -INFINITY, ymn = INFINITY, ymx = -INFINITY;
    #pragma unroll 1
    for (int n = tid; n < NFULL; n += THREADS){
        float a = x[n], b = y[n];
        xmn = fminf(xmn, a); xmx = fmaxf(xmx, a);
        ymn = fminf(ymn, b); ymx = fmaxf(ymx, b);
    }
    #pragma unroll
    for (int o = 16; o; o >>= 1){
        xmn = fminf(xmn, __shfl_down_sync(0xffffffffu, xmn, o));
        xmx = fmaxf(xmx, __shfl_down_sync(0xffffffffu, xmx, o));
        ymn = fminf(ymn, __shfl_down_sync(0xffffffffu, ymn, o));
        ymx = fmaxf(ymx, __shfl_down_sync(0xffffffffu, ymx, o));
    }
    if (lane == 0){ s_red[warp][0]=xmn; s_red[warp][1]=xmx; s_red[warp][2]=ymn; s_red[warp][3]=ymx; }
    __syncthreads();
    if (tid == 0){
        float a = s_red[0][0], b = s_red[0][1], c = s_red[0][2], d = s_red[0][3];
        for (int w = 1; w < 16; w++){
            a = fminf(a, s_red[w][0]); b = fmaxf(b, s_red[w][1]);
            c = fminf(c, s_red[w][2]); d = fmaxf(d, s_red[w][3]);
        }
        s_mm[0]=a; s_mm[1]=b; s_mm[2]=c; s_mm[3]=d;
    }
    __syncthreads();

    const float xmin = s_mm[0], ymin = s_mm[2];
    const float bwx = __fdiv_rn(s_mm[1] - s_mm[0], 10.0f);
    const float bwy = __fdiv_rn(s_mm[3] - s_mm[2], 10.0f);

    #pragma unroll 1
    for (int n = tid; n < NFULL; n += THREADS){
        int ix = (int)__fdiv_rn(x[n] - xmin, bwx);
        int iy = (int)__fdiv_rn(y[n] - ymin, bwy);
        ix = min(max(ix, 0), 9);
        iy = min(max(iy, 0), 9);
        atomicAdd(&hist[ix * 10 + iy], 1u);
    }
    __syncthreads();

    if (tid == 0){
        const float eps = 1e-8f;
        const float denom = 8388608.0f;  // B*S = 512*16384 (faithful to reference)
        float hx[10], hy[10];
        for (int a = 0; a < 10; a++){ hx[a] = 0.f; hy[a] = 0.f; }
        for (int a = 0; a < 10; a++)
            for (int b = 0; b < 10; b++){
                float h = (float)hist[a*10 + b];
                hx[a] += h; hy[b] += h;
            }
        float mi = 0.f;
        for (int a = 0; a < 10; a++){
            float px = hx[a] / denom;
            for (int b = 0; b < 10; b++){
                float py  = hy[b] / denom;
                float pxy = (float)hist[a*10 + b] / denom;
                mi += pxy * logf(__fdiv_rn(pxy + eps, px * py + eps));
            }
        }
        float hxe = 0.f, hye = 0.f;
        for (int a = 0; a < 10; a++){
            float px = hx[a] / denom, py = hy[a] / denom;
            hxe -= px * logf(px + eps);
            hye -= py * logf(py + eps);
        }
        float nmi = mi / (0.5f * (hxe + hye));
        atomicAdd(&g_nmi, (double)nmi);
    }
}

// ---------------- finalize ----------------
__global__ void finalize_kernel(const int* __restrict__ pep, float* __restrict__ out){
    double loss = g_pear / (double)ROWS;
    int ep = *pep;
    if (ep >= 400){
        loss += 1.0 - g_cos / (double)ROWS;     // phase correlation
        loss += g_absdiff / g_tp;               // power spectrum
    }
    if (ep >= 700){
        loss += 1.0 - g_nmi / (double)ROWS;     // mutual information
    }
    out[0] = (float)loss;
}

// ---------------- launch ----------------
extern "C" void kernel_launch(void* const* d_in, const int* in_sizes, int n_in,
                              void* d_out, int out_size){
    const float* pred = (const float*)d_in[0];
    const float* targ = (const float*)d_in[1];
    const int*   pi   = (const int*)d_in[2];
    const int*   pep  = (const int*)d_in[3];
    float* out = (float*)d_out;

    const size_t smem_bytes = (size_t)(2*M + NBINS + 2048) * sizeof(float2); // 213000
    cudaFuncSetAttribute(row_kernel, cudaFuncAttributeMaxDynamicSharedMemorySize,
                         (int)smem_bytes);

    zero_acc_kernel<<<1, 1>>>();
    init_tw_kernel<<<(NBINS + 255) / 256, 256>>>();
    row_kernel<<<ROWS, THREADS, smem_bytes>>>(pred, targ, pi);
    mi_kernel<<<ROWS, THREADS>>>(pred, targ, pi);
    finalize_kernel<<<1, 1>>>(pep, out);
}

// round 3
// speedup vs baseline: 2.6018x; 2.6018x over previous
#include <cuda_runtime.h>
#include <math.h>
#include <stdint.h>

#define THREADS 512
#define M 8192            // packed complex FFT size
#define NFULL 16384       // real signal length
#define NBINS 8193        // rfft bins
#define ROWS 512
#define PI_D 3.14159265358979323846

// ---------------- global accumulators / tables (no allocation allowed) ---------
__device__ double g_pear;
__device__ double g_cos;
__device__ double g_absdiff;
__device__ double g_tp;
__device__ double g_nmi;

__device__ float2 g_W2048[2048];    // e^{-2pi i k/8192}, k<2048 (rest by symmetry)
__device__ float2 g_WN[NBINS];      // e^{-i pi k/8192},  k=0..8192

// ---------------- complex helpers ----------------
__device__ __forceinline__ float2 cmul(float2 a, float2 b){
    return make_float2(a.x*b.x - a.y*b.y, a.x*b.y + a.y*b.x);
}
__device__ __forceinline__ float2 cadd(float2 a, float2 b){ return make_float2(a.x+b.x, a.y+b.y); }
__device__ __forceinline__ float2 csub(float2 a, float2 b){ return make_float2(a.x-b.x, a.y-b.y); }
__device__ __forceinline__ float2 cconj(float2 a){ return make_float2(a.x, -a.y); }

__device__ __forceinline__ float warp_sum(float v){
    #pragma unroll
    for (int o = 16; o; o >>= 1) v += __shfl_down_sync(0xffffffffu, v, o);
    return v;
}

// ---------------- init kernels ----------------
__global__ void zero_acc_kernel(){
    g_pear = 0.0; g_cos = 0.0; g_absdiff = 0.0; g_tp = 0.0; g_nmi = 0.0;
}

__global__ void init_tw_kernel(){
    int k = blockIdx.x * blockDim.x + threadIdx.x;
    if (k < 2048){
        double a = -2.0 * PI_D * (double)k / 8192.0;
        g_W2048[k] = make_float2((float)cos(a), (float)sin(a));
    }
    if (k < NBINS){
        double a = -PI_D * (double)k / 8192.0;
        g_WN[k] = make_float2((float)cos(a), (float)sin(a));
    }
}

// twiddle fetch: W_8192^k for k in [0,4096), table holds k<2048
__device__ __forceinline__ float2 twget(const float2* __restrict__ W, int k, int inv){
    float2 w = W[k & 2047];
    float2 r = (k & 2048) ? make_float2(w.y, -w.x) : w;   // * e^{-i pi/2}
    if (inv) r.y = -r.y;
    return r;
}

// ---------------- FFT 8192, DIT, bit-reversed input ----------------
// 6 merged radix-4 passes (stage pairs 1-2 .. 11-12) + 1 final radix-2 (stage 13).
// If B != nullptr, both arrays are transformed sharing the same barriers.
__device__ void fft8192(float2* A, float2* B, const float2* __restrict__ W, int inv){
    #pragma unroll 1
    for (int p = 0; p < 6; p++){
        const int h = 1 << (2*p);
        #pragma unroll
        for (int it = 0; it < 4; it++){
            int q = threadIdx.x + it * THREADS;
            int t = q & (h - 1);
            int base = ((q >> (2*p)) << (2*p + 2)) + t;
            float2 W1 = twget(W, t << (12 - 2*p), inv);
            float2 W2 = twget(W, t << (11 - 2*p), inv);
            float2 W3 = inv ? make_float2(-W2.y, W2.x) : make_float2(W2.y, -W2.x); // ±i*W2
            {
                float2 a0 = A[base], a1 = A[base + h], a2 = A[base + 2*h], a3 = A[base + 3*h];
                float2 u1 = cmul(a1, W1), u3 = cmul(a3, W1);
                float2 b0 = cadd(a0, u1), b1 = csub(a0, u1);
                float2 b2 = cadd(a2, u3), b3 = csub(a2, u3);
                float2 v2 = cmul(b2, W2), v3 = cmul(b3, W3);
                A[base]       = cadd(b0, v2);
                A[base + 2*h] = csub(b0, v2);
                A[base + h]   = cadd(b1, v3);
                A[base + 3*h] = csub(b1, v3);
            }
            if (B){
                float2 a0 = B[base], a1 = B[base + h], a2 = B[base + 2*h], a3 = B[base + 3*h];
                float2 u1 = cmul(a1, W1), u3 = cmul(a3, W1);
                float2 b0 = cadd(a0, u1), b1 = csub(a0, u1);
                float2 b2 = cadd(a2, u3), b3 = csub(a2, u3);
                float2 v2 = cmul(b2, W2), v3 = cmul(b3, W3);
                B[base]       = cadd(b0, v2);
                B[base + 2*h] = csub(b0, v2);
                B[base + h]   = cadd(b1, v3);
                B[base + 3*h] = csub(b1, v3);
            }
        }
        __syncthreads();
    }
    // final radix-2 stage: h = 4096
    #pragma unroll
    for (int it = 0; it < 8; it++){
        int j = threadIdx.x + it * THREADS;
        float2 w = twget(W, j, inv);
        {
            float2 u = A[j], v = cmul(A[j + 4096], w);
            A[j] = cadd(u, v); A[j + 4096] = csub(u, v);
        }
        if (B){
            float2 u = B[j], v = cmul(B[j + 4096], w);
            B[j] = cadd(u, v); B[j + 4096] = csub(u, v);
        }
    }
    __syncthreads();
}

// Unpack: X[k] of the length-16384 real signal from packed Z.
// w must be e^{-i pi k/8192}; valid for k in [0, 8192].
__device__ __forceinline__ float2 spec_at(const float2* Z, int k, float2 w){
    float2 a = Z[k & (M - 1)];
    float2 b = Z[(M - k) & (M - 1)];
    float2 E = make_float2(0.5f*(a.x + b.x),  0.5f*(a.y - b.y));
    float2 O = make_float2(0.5f*(a.y + b.y), -0.5f*(a.x - b.x));
    float2 WO = cmul(w, O);
    return make_float2(E.x + WO.x, E.y + WO.y);
}

// ---------------- main fused kernel: one CTA per row ----------------
__global__ __launch_bounds__(THREADS, 1)
void row_kernel(const float* __restrict__ pred, const float* __restrict__ targ,
                const int* __restrict__ pi){
    extern __shared__ float2 sm[];
    float2* Zp = sm;                    // 8192
    float2* Zt = sm + M;                // 8192
    float2* Cb = sm + 2*M;              // 8193
    float2* Wt = sm + 2*M + NBINS;      // 2048

    __shared__ float    s_red[16][10];
    __shared__ int      s_idx[16];
    __shared__ float    s_mm[4];        // xmin,xmax,ymin,ymax
    __shared__ unsigned hist[100];
    __shared__ float    s_hx[10], s_hy[10];

    const int tid  = threadIdx.x;
    const int warp = tid >> 5, lane = tid & 31;
    const int row  = blockIdx.x;
    const int i0   = *pi;

    const float2* xr = (const float2*)(pred + ((size_t)i0 * ROWS + row) * (size_t)NFULL);
    const float2* yr = (const float2*)(targ + (size_t)row * (size_t)NFULL);

    if (tid < 100) hist[tid] = 0u;

    // twiddle table -> smem
    #pragma unroll
    for (int it = 0; it < 4; it++) Wt[tid + it*THREADS] = g_W2048[tid + it*THREADS];

    // ---- load (bit-reversed pack) + Pearson moments + min/max ----
    float sx = 0.f, sy = 0.f, sxy = 0.f, sx2 = 0.f, sy2 = 0.f;
    float xmn = INFINITY, xmx = -INFINITY, ymn = INFINITY, ymx = -INFINITY;
    #pragma unroll 4
    for (int it = 0; it < 16; it++){
        int n = tid + it * THREADS;
        float2 a = xr[n], b = yr[n];
        sx  += a.x + a.y;          sy  += b.x + b.y;
        sxy += a.x*b.x + a.y*b.y;
        sx2 += a.x*a.x + a.y*a.y;  sy2 += b.x*b.x + b.y*b.y;
        xmn = fminf(xmn, fminf(a.x, a.y)); xmx = fmaxf(xmx, fmaxf(a.x, a.y));
        ymn = fminf(ymn, fminf(b.x, b.y)); ymx = fmaxf(ymx, fmaxf(b.x, b.y));
        int r = __brev(n) >> 19;   // 13-bit reversal
        Zp[r] = a; Zt[r] = b;
    }
    sx  = warp_sum(sx);  sy  = warp_sum(sy); sxy = warp_sum(sxy);
    sx2 = warp_sum(sx2); sy2 = warp_sum(sy2);
    #pragma unroll
    for (int o = 16; o; o >>= 1){
        xmn = fminf(xmn, __shfl_down_sync(0xffffffffu, xmn, o));
        xmx = fmaxf(xmx, __shfl_down_sync(0xffffffffu, xmx, o));
        ymn = fminf(ymn, __shfl_down_sync(0xffffffffu, ymn, o));
        ymx = fmaxf(ymx, __shfl_down_sync(0xffffffffu, ymx, o));
    }
    if (lane == 0){
        s_red[warp][0]=sx;  s_red[warp][1]=sy;  s_red[warp][2]=sxy;
        s_red[warp][3]=sx2; s_red[warp][4]=sy2;
        s_red[warp][5]=xmn; s_red[warp][6]=xmx; s_red[warp][7]=ymn; s_red[warp][8]=ymx;
    }
    __syncthreads();
    if (tid == 0){
        double Sx=0,Sy=0,Sxy=0,Sx2=0,Sy2=0;
        float a = s_red[0][5], b = s_red[0][6], c = s_red[0][7], d = s_red[0][8];
        for (int w = 0; w < 16; w++){
            Sx+=s_red[w][0]; Sy+=s_red[w][1]; Sxy+=s_red[w][2];
            Sx2+=s_red[w][3]; Sy2+=s_red[w][4];
            a = fminf(a, s_red[w][5]); b = fmaxf(b, s_red[w][6]);
            c = fminf(c, s_red[w][7]); d = fmaxf(d, s_red[w][8]);
        }
        const double N = (double)NFULL;
        double pear = (N*Sxy - Sx*Sy) / sqrt((N*Sx2 - Sx*Sx) * (N*Sy2 - Sy*Sy));
        atomicAdd(&g_pear, 1.0 - pear);
        s_mm[0]=a; s_mm[1]=b; s_mm[2]=c; s_mm[3]=d;
    }
    __syncthreads();

    // ---- MI histogram from smem-resident data (order-invariant; pairing preserved) ----
    {
        const float xmin = s_mm[0], ymin = s_mm[2];
        const float bwx = __fdiv_rn(s_mm[1] - s_mm[0], 10.0f);
        const float bwy = __fdiv_rn(s_mm[3] - s_mm[2], 10.0f);
        #pragma unroll 4
        for (int it = 0; it < 16; it++){
            int n = tid + it * THREADS;
            float2 a = Zp[n], b = Zt[n];
            int ix0 = min(max((int)__fdiv_rn(a.x - xmin, bwx), 0), 9);
            int iy0 = min(max((int)__fdiv_rn(b.x - ymin, bwy), 0), 9);
            int ix1 = min(max((int)__fdiv_rn(a.y - xmin, bwx), 0), 9);
            int iy1 = min(max((int)__fdiv_rn(b.y - ymin, bwy), 0), 9);
            atomicAdd(&hist[ix0 * 10 + iy0], 1u);
            atomicAdd(&hist[ix1 * 10 + iy1], 1u);
        }
    }
    __syncthreads();

    // ---- MI final math on warp 0 (others proceed into FFT; hist untouched) ----
    if (warp == 0){
        const float eps = 1e-8f;
        const float invD = 1.0f / 8388608.0f;   // 1/(B*S), faithful to reference
        if (lane < 10){
            float hx = 0.f, hy = 0.f;
            for (int j = 0; j < 10; j++){
                hx += (float)hist[lane*10 + j];
                hy += (float)hist[j*10 + lane];
            }
            s_hx[lane] = hx; s_hy[lane] = hy;
        }
        __syncwarp();
        float mi = 0.f;
        for (int b = lane; b < 100; b += 32){
            float px  = s_hx[b/10] * invD;
            float py  = s_hy[b%10] * invD;
            float pxy = (float)hist[b] * invD;
            mi += pxy * logf(__fdiv_rn(pxy + eps, px * py + eps));
        }
        mi = warp_sum(mi);
        float he = 0.f;
        if (lane < 10){
            float px = s_hx[lane] * invD, py = s_hy[lane] * invD;
            he = -px * logf(px + eps) - py * logf(py + eps);
        }
        he = warp_sum(he);
        if (lane == 0) atomicAdd(&g_nmi, (double)(mi / (0.5f * he)));
    }

    // ---- forward FFTs, shared barriers for both arrays ----
    fft8192(Zp, Zt, Wt, 0);

    // ---- spectra: power-spectrum sums + hann-windowed phase correlation ----
    // Neighbor spectra X[k-1]/X[k+1] fetched from adjacent lanes via shuffle.
    float accd = 0.f, acct = 0.f;
    float2 lastX0p, lastX0t, lastXpp, lastXpt;
    for (int it = 0; it < 16; it++){
        int k = tid + it * THREADS;            // 0..8191
        float2 w0 = g_WN[k];
        float2 X0p = spec_at(Zp, k, w0);
        float2 X0t = spec_at(Zt, k, w0);
        float2 Xmp, Xmt, Xpp, Xpt;
        Xmp.x = __shfl_up_sync(0xffffffffu, X0p.x, 1);
        Xmp.y = __shfl_up_sync(0xffffffffu, X0p.y, 1);
        Xmt.x = __shfl_up_sync(0xffffffffu, X0t.x, 1);
        Xmt.y = __shfl_up_sync(0xffffffffu, X0t.y, 1);
        Xpp.x = __shfl_down_sync(0xffffffffu, X0p.x, 1);
        Xpp.y = __shfl_down_sync(0xffffffffu, X0p.y, 1);
        Xpt.x = __shfl_down_sync(0xffffffffu, X0t.x, 1);
        Xpt.y = __shfl_down_sync(0xffffffffu, X0t.y, 1);
        if (lane == 0){
            if (k == 0){
                float2 w1 = g_WN[1];
                Xmp = cconj(spec_at(Zp, 1, w1));   // X[-1] = conj(X[1])
                Xmt = cconj(spec_at(Zt, 1, w1));
            } else {
                float2 wm = g_WN[k-1];
                Xmp = spec_at(Zp, k-1, wm);
                Xmt = spec_at(Zt, k-1, wm);
            }
        }
        if (lane == 31){
            float2 wp = g_WN[k+1];                 // k+1 <= 8192
            Xpp = spec_at(Zp, k+1, wp);
            Xpt = spec_at(Zt, k+1, wp);
        }
        float pp = X0p.x*X0p.x + X0p.y*X0p.y;
        float pt = X0t.x*X0t.x + X0t.y*X0t.y;
        accd += fabsf(pp - pt);
        acct += pt;
        float2 xf = make_float2(0.5f*X0p.x - 0.25f*(Xmp.x + Xpp.x),
                                0.5f*X0p.y - 0.25f*(Xmp.y + Xpp.y));
        float2 tf = make_float2(0.5f*X0t.x - 0.25f*(Xmt.x + Xpt.x),
                                0.5f*X0t.y - 0.25f*(Xmt.y + Xpt.y));
        float2 c = cmul(xf, cconj(tf));
        float inv = rsqrtf(c.x*c.x + c.y*c.y);
        Cb[k] = make_float2(c.x*inv, c.y*inv);
        lastX0p = X0p; lastX0t = X0t; lastXpp = Xpp; lastXpt = Xpt;
    }
    if (tid == THREADS - 1){
        // bin k = 8192: X0' = X[8192] (= lastXpp), Xm' = X[8191], Xp' = conj(X[8191])
        float2 X0p = lastXpp, X0t = lastXpt;
        float2 Xmp = lastX0p, Xmt = lastX0t;
        float2 Xpp = cconj(Xmp), Xpt = cconj(Xmt);
        float pp = X0p.x*X0p.x + X0p.y*X0p.y;
        float pt = X0t.x*X0t.x + X0t.y*X0t.y;
        accd += fabsf(pp - pt);
        acct += pt;
        float2 xf = make_float2(0.5f*X0p.x - 0.25f*(Xmp.x + Xpp.x),
                                0.5f*X0p.y - 0.25f*(Xmp.y + Xpp.y));
        float2 tf = make_float2(0.5f*X0t.x - 0.25f*(Xmt.x + Xpt.x),
                                0.5f*X0t.y - 0.25f*(Xmt.y + Xpt.y));
        float2 c = cmul(xf, cconj(tf));
        float inv = rsqrtf(c.x*c.x + c.y*c.y);
        Cb[8192] = make_float2(c.x*inv, c.y*inv);
    }
    accd = warp_sum(accd); acct = warp_sum(acct);
    if (lane == 0){ s_red[warp][0] = accd; s_red[warp][1] = acct; }
    __syncthreads();
    if (tid == 0){
        double d = 0.0, t2 = 0.0;
        for (int w = 0; w < 16; w++){ d += s_red[w][0]; t2 += s_red[w][1]; }
        atomicAdd(&g_absdiff, d);
        atomicAdd(&g_tp, t2);
    }
    __syncthreads();

    // ---- pack spectrum back for real inverse FFT (into Zp, bit-reversed) ----
    #pragma unroll 4
    for (int it = 0; it < 16; it++){
        int k = tid + it * THREADS;
        float2 Ck  = Cb[k];
        float2 Ck2 = (k == 0) ? Cb[8192] : cconj(Cb[8192 - k]);  // C[k+8192]
        float2 E = make_float2(0.5f*(Ck.x + Ck2.x), 0.5f*(Ck.y + Ck2.y));
        float2 D = make_float2(0.5f*(Ck.x - Ck2.x), 0.5f*(Ck.y - Ck2.y));
        float2 wn = cconj(g_WN[k]);             // e^{+i pi k/8192}
        float2 O  = cmul(wn, D);
        Zp[__brev(k) >> 19] = make_float2(E.x - O.y, E.y + O.x);  // E + i*O
    }
    __syncthreads();
    fft8192(Zp, (float2*)0, Wt, 1);   // unnormalized IDFT; positive scale -> argmax invariant

    // ---- argmax over 16384 real samples (first-occurrence tie break) ----
    float best = -INFINITY; int bi = 0x7fffffff;
    #pragma unroll 4
    for (int it = 0; it < 16; it++){
        int n = tid + it * THREADS;
        float2 z = Zp[n];                 // y[2n] = Re, y[2n+1] = Im
        int e = 2*n, o = 2*n + 1;
        if (z.x > best || (z.x == best && e < bi)){ best = z.x; bi = e; }
        if (z.y > best || (z.y == best && o < bi)){ best = z.y; bi = o; }
    }
    #pragma unroll
    for (int off = 16; off; off >>= 1){
        float ov = __shfl_down_sync(0xffffffffu, best, off);
        int   oi = __shfl_down_sync(0xffffffffu, bi,   off);
        if (ov > best || (ov == best && oi < bi)){ best = ov; bi = oi; }
    }
    if (lane == 0){ s_red[warp][0] = best; s_idx[warp] = bi; }
    __syncthreads();
    if (tid == 0){
        best = s_red[0][0]; bi = s_idx[0];
        for (int w = 1; w < 16; w++){
            float v = s_red[w][0]; int ix = s_idx[w];
            if (v > best || (v == best && ix < bi)){ best = v; bi = ix; }
        }
        atomicAdd(&g_cos, (double)cosf(2.0f * (float)PI_D * (float)bi / 16384.0f));
    }
}

// ---------------- finalize ----------------
__global__ void finalize_kernel(const int* __restrict__ pep, float* __restrict__ out){
    double loss = g_pear / (double)ROWS;
    int ep = *pep;
    if (ep >= 400){
        loss += 1.0 - g_cos / (double)ROWS;     // phase correlation
        loss += g_absdiff / g_tp;               // power spectrum
    }
    if (ep >= 700){
        loss += 1.0 - g_nmi / (double)ROWS;     // mutual information
    }
    out[0] = (float)loss;
}

// ---------------- launch ----------------
extern "C" void kernel_launch(void* const* d_in, const int* in_sizes, int n_in,
                              void* d_out, int out_size){
    const float* pred = (const float*)d_in[0];
    const float* targ = (const float*)d_in[1];
    const int*   pi   = (const int*)d_in[2];
    const int*   pep  = (const int*)d_in[3];
    float* out = (float*)d_out;

    const size_t smem_bytes = (size_t)(2*M + NBINS + 2048) * sizeof(float2); // 213000
    cudaFuncSetAttribute(row_kernel, cudaFuncAttributeMaxDynamicSharedMemorySize,
                         (int)smem_bytes);

    zero_acc_kernel<<<1, 1>>>();
    init_tw_kernel<<<(NBINS + 255) / 256, 256>>>();
    row_kernel<<<ROWS, THREADS, smem_bytes>>>(pred, targ, pi);
    finalize_kernel<<<1, 1>>>(pep, out);
}

// round 5
// speedup vs baseline: 3.7396x; 1.4373x over previous
#include <cuda_runtime.h>
#include <math.h>
#include <stdint.h>

#define THREADS 512
#define M 8192            // packed complex FFT size
#define NFULL 16384       // real signal length
#define NBINS 8193
#define ROWS 512
#define PI_D 3.14159265358979323846

// ---------------- global accumulators / tables ----------------
__device__ double g_pear;
__device__ double g_cos;
__device__ double g_absdiff;
__device__ double g_tp;
__device__ double g_nmi;

__device__ float2 g_W2048[2048];    // e^{-2pi i k/8192}, k<2048
__device__ float2 g_WN[NBINS];      // e^{-i pi k/8192},  k=0..8192

// ---------------- complex helpers ----------------
__device__ __forceinline__ float2 cmul(float2 a, float2 b){
    return make_float2(a.x*b.x - a.y*b.y, a.x*b.y + a.y*b.x);
}
__device__ __forceinline__ float2 cadd(float2 a, float2 b){ return make_float2(a.x+b.x, a.y+b.y); }
__device__ __forceinline__ float2 csub(float2 a, float2 b){ return make_float2(a.x-b.x, a.y-b.y); }
__device__ __forceinline__ float2 cconj(float2 a){ return make_float2(a.x, -a.y); }

__device__ __forceinline__ float warp_sum(float v){
    #pragma unroll
    for (int o = 16; o; o >>= 1) v += __shfl_down_sync(0xffffffffu, v, o);
    return v;
}

// ---------------- init ----------------
__global__ void init_tw_kernel(){
    int k = blockIdx.x * blockDim.x + threadIdx.x;
    if (k == 0){ g_pear = 0.0; g_cos = 0.0; g_absdiff = 0.0; g_tp = 0.0; g_nmi = 0.0; }
    if (k < 2048){
        double a = -2.0 * PI_D * (double)k / 8192.0;
        g_W2048[k] = make_float2((float)cos(a), (float)sin(a));
    }
    if (k < NBINS){
        double a = -PI_D * (double)k / 8192.0;
        g_WN[k] = make_float2((float)cos(a), (float)sin(a));
    }
}

// twiddle fetch: W_8192^k, k in [0, 8192)
template<int INV>
__device__ __forceinline__ float2 twget(const float2* __restrict__ Wt, int k){
    float2 w = Wt[k & 2047];
    int q = k >> 11;
    float2 r = (q & 1) ? make_float2(w.y, -w.x) : w;
    if (q & 2){ r.x = -r.x; r.y = -r.y; }
    if (INV) r.y = -r.y;
    return r;
}

template<int INV>
__device__ __forceinline__ float2 cmulK(float2 a, float wr, float wi){
    float i2 = INV ? -wi : wi;
    return make_float2(a.x*wr - a.y*i2, a.x*i2 + a.y*wr);
}

// radix-4 DIT butterfly
template<int INV>
__device__ __forceinline__ void bfly4(float2 b0, float2 b1, float2 b2, float2 b3,
                                      float2& o0, float2& o1, float2& o2, float2& o3){
    float2 s  = cadd(b0, b2), d  = csub(b0, b2);
    float2 s2 = cadd(b1, b3), d2 = csub(b1, b3);
    o0 = cadd(s, s2); o2 = csub(s, s2);
    if (!INV){ o1 = make_float2(d.x + d2.y, d.y - d2.x); o3 = make_float2(d.x - d2.y, d.y + d2.x); }
    else     { o1 = make_float2(d.x - d2.y, d.y + d2.x); o3 = make_float2(d.x + d2.y, d.y - d2.x); }
}

// 16-point FFT in registers, natural in/out (two radix-4 micro-passes)
template<int INV>
__device__ __forceinline__ void fft16(float2* x){
    float2 t[16];
    #pragma unroll
    for (int g = 0; g < 4; g++)
        bfly4<INV>(x[g], x[g+4], x[g+8], x[g+12], t[4*g], t[4*g+1], t[4*g+2], t[4*g+3]);
    const float C1 = 0.9238795325112867f, S1 = 0.3826834323650898f, R2 = 0.7071067811865476f;
    bfly4<INV>(t[0], t[4], t[8], t[12], x[0], x[4], x[8], x[12]);
    bfly4<INV>(t[1], cmulK<INV>(t[5],  C1, -S1), cmulK<INV>(t[9],  R2, -R2), cmulK<INV>(t[13],  S1, -C1),
               x[1], x[5], x[9], x[13]);
    bfly4<INV>(t[2], cmulK<INV>(t[6],  R2, -R2), cmulK<INV>(t[10], 0.f, -1.f), cmulK<INV>(t[14], -R2, -R2),
               x[2], x[6], x[10], x[14]);
    bfly4<INV>(t[3], cmulK<INV>(t[7],  S1, -C1), cmulK<INV>(t[11], -R2, -R2), cmulK<INV>(t[15], -C1,  S1),
               x[3], x[7], x[11], x[15]);
}

// Stockham radix-16 pass (L=1, twiddle-free): in[j+512c] -> out[16j+c]
template<int INV>
__device__ __forceinline__ void pass16(const float* __restrict__ ri, const float* __restrict__ ii,
                                       float* __restrict__ ro, float* __restrict__ io){
    int j = threadIdx.x;
    float2 x[16];
    #pragma unroll
    for (int c = 0; c < 16; c++){ x[c].x = ri[j + 512*c]; x[c].y = ii[j + 512*c]; }
    fft16<INV>(x);
    #pragma unroll
    for (int q = 0; q < 4; q++){
        ((float4*)(ro + 16*j))[q] = make_float4(x[4*q].x, x[4*q+1].x, x[4*q+2].x, x[4*q+3].x);
        ((float4*)(io + 16*j))[q] = make_float4(x[4*q].y, x[4*q+1].y, x[4*q+2].y, x[4*q+3].y);
    }
}

// Stockham radix-4 pass at sub-length L = 2^LOG2L
template<int LOG2L, int INV>
__device__ __forceinline__ void pass4(const float* __restrict__ ri, const float* __restrict__ ii,
                                      float* __restrict__ ro, float* __restrict__ io,
                                      const float2* __restrict__ Wt){
    const int L = 1 << LOG2L;
    const int TSTEP = 1 << (11 - LOG2L);
    #pragma unroll
    for (int it = 0; it < 4; it++){
        int j = threadIdx.x + it * 512;
        int r = j & (L - 1);
        int base = ((j >> LOG2L) << (LOG2L + 2)) + r;
        float2 a0 = make_float2(ri[j],        ii[j]);
        float2 a1 = make_float2(ri[j + 2048], ii[j + 2048]);
        float2 a2 = make_float2(ri[j + 4096], ii[j + 4096]);
        float2 a3 = make_float2(ri[j + 6144], ii[j + 6144]);
        int tw = r * TSTEP;
        float2 b1 = cmul(a1, twget<INV>(Wt, tw));
        float2 b2 = cmul(a2, twget<INV>(Wt, 2*tw));
        float2 b3 = cmul(a3, twget<INV>(Wt, 3*tw));
        float2 o0, o1, o2, o3;
        bfly4<INV>(a0, b1, b2, b3, o0, o1, o2, o3);
        ro[base]       = o0.x; io[base]       = o0.y;
        ro[base + L]   = o1.x; io[base + L]   = o1.y;
        ro[base + 2*L] = o2.x; io[base + 2*L] = o2.y;
        ro[base + 3*L] = o3.x; io[base + 3*L] = o3.y;
    }
}

// final Stockham radix-2 pass (L=4096)
template<int INV>
__device__ __forceinline__ void pass2(const float* __restrict__ ri, const float* __restrict__ ii,
                                      float* __restrict__ ro, float* __restrict__ io,
                                      const float2* __restrict__ Wt){
    #pragma unroll
    for (int it = 0; it < 8; it++){
        int j = threadIdx.x + it * 512;
        float2 a = make_float2(ri[j], ii[j]);
        float2 b = make_float2(ri[j + 4096], ii[j + 4096]);
        float2 v = cmul(b, twget<INV>(Wt, j));
        ro[j] = a.x + v.x;        io[j] = a.y + v.y;
        ro[j + 4096] = a.x - v.x; io[j + 4096] = a.y - v.y;
    }
}

// unpack X[k] of the length-16384 real signal from packed spectrum planes
__device__ __forceinline__ float2 spec_at(const float* __restrict__ re, const float* __restrict__ im,
                                          int k, float2 w){
    int k1 = k & (M - 1), k2 = (M - k) & (M - 1);
    float2 a = make_float2(re[k1], im[k1]);
    float2 b = make_float2(re[k2], im[k2]);
    float2 E = make_float2(0.5f*(a.x + b.x),  0.5f*(a.y - b.y));
    float2 O = make_float2(0.5f*(a.y + b.y), -0.5f*(a.x - b.x));
    float2 WO = cmul(w, O);
    return make_float2(E.x + WO.x, E.y + WO.y);
}

// ---------------- main fused kernel: one CTA per row ----------------
__global__ __launch_bounds__(THREADS, 1)
void row_kernel(const float* __restrict__ pred, const float* __restrict__ targ,
                const int* __restrict__ pi){
    extern __shared__ float smf[];
    float* Ar = smf;
    float* Ai = smf + 8192;
    float* Br = smf + 16384;
    float* Bi = smf + 24576;
    float* Cr = smf + 32768;
    float* Ci = smf + 40960;
    float2* Wt = (float2*)(smf + 49152);   // 2048 float2

    __shared__ float    s_red[16][10];
    __shared__ int      s_idx[16];
    __shared__ float    s_mm[4];
    __shared__ unsigned hist[100];
    __shared__ float    s_hx[10], s_hy[10];
    __shared__ float2   s_c8192;

    const int tid  = threadIdx.x;
    const int warp = tid >> 5, lane = tid & 31;
    const int row  = blockIdx.x;
    const int i0   = *pi;

    const float2* xr = (const float2*)(pred + ((size_t)i0 * ROWS + row) * (size_t)NFULL);
    const float2* yr = (const float2*)(targ + (size_t)row * (size_t)NFULL);

    if (tid < 100) hist[tid] = 0u;
    #pragma unroll
    for (int it = 0; it < 4; it++) Wt[tid + it*THREADS] = g_W2048[tid + it*THREADS];

    // ---- load (SoA natural order) + Pearson moments + min/max ----
    float sx = 0.f, sy = 0.f, sxy = 0.f, sx2 = 0.f, sy2 = 0.f;
    float xmn = INFINITY, xmx = -INFINITY, ymn = INFINITY, ymx = -INFINITY;
    #pragma unroll 4
    for (int it = 0; it < 16; it++){
        int n = tid + it * THREADS;
        float2 a = xr[n], b = yr[n];
        sx  += a.x + a.y;          sy  += b.x + b.y;
        sxy += a.x*b.x + a.y*b.y;
        sx2 += a.x*a.x + a.y*a.y;  sy2 += b.x*b.x + b.y*b.y;
        xmn = fminf(xmn, fminf(a.x, a.y)); xmx = fmaxf(xmx, fmaxf(a.x, a.y));
        ymn = fminf(ymn, fminf(b.x, b.y)); ymx = fmaxf(ymx, fmaxf(b.x, b.y));
        Ar[n] = a.x; Ai[n] = a.y;
        Br[n] = b.x; Bi[n] = b.y;
    }
    sx  = warp_sum(sx);  sy  = warp_sum(sy); sxy = warp_sum(sxy);
    sx2 = warp_sum(sx2); sy2 = warp_sum(sy2);
    #pragma unroll
    for (int o = 16; o; o >>= 1){
        xmn = fminf(xmn, __shfl_down_sync(0xffffffffu, xmn, o));
        xmx = fmaxf(xmx, __shfl_down_sync(0xffffffffu, xmx, o));
        ymn = fminf(ymn, __shfl_down_sync(0xffffffffu, ymn, o));
        ymx = fmaxf(ymx, __shfl_down_sync(0xffffffffu, ymx, o));
    }
    if (lane == 0){
        s_red[warp][0]=sx;  s_red[warp][1]=sy;  s_red[warp][2]=sxy;
        s_red[warp][3]=sx2; s_red[warp][4]=sy2;
        s_red[warp][5]=xmn; s_red[warp][6]=xmx; s_red[warp][7]=ymn; s_red[warp][8]=ymx;
    }
    __syncthreads();
    if (tid == 0){
        double Sx=0,Sy=0,Sxy=0,Sx2=0,Sy2=0;
        float a = s_red[0][5], b = s_red[0][6], c = s_red[0][7], d = s_red[0][8];
        for (int w = 0; w < 16; w++){
            Sx+=s_red[w][0]; Sy+=s_red[w][1]; Sxy+=s_red[w][2];
            Sx2+=s_red[w][3]; Sy2+=s_red[w][4];
            a = fminf(a, s_red[w][5]); b = fmaxf(b, s_red[w][6]);
            c = fminf(c, s_red[w][7]); d = fmaxf(d, s_red[w][8]);
        }
        const double N = (double)NFULL;
        double pear = (N*Sxy - Sx*Sy) / sqrt((N*Sx2 - Sx*Sx) * (N*Sy2 - Sy*Sy));
        atomicAdd(&g_pear, 1.0 - pear);
        s_mm[0]=a; s_mm[1]=b; s_mm[2]=c; s_mm[3]=d;
    }
    __syncthreads();

    // ---- forward FFT chain (pred): A <-> C, with MI histogram fused in pass 1 ----
    {
        const float xmin = s_mm[0], ymin = s_mm[2];
        const float bwx = __fdiv_rn(s_mm[1] - s_mm[0], 10.0f);
        const float bwy = __fdiv_rn(s_mm[3] - s_mm[2], 10.0f);
        int j = tid;
        float2 x[16];
        #pragma unroll
        for (int c = 0; c < 16; c++){
            int n = j + 512*c;
            float2 a = make_float2(Ar[n], Ai[n]);
            float2 b = make_float2(Br[n], Bi[n]);
            x[c] = a;
            int ix0 = min(max((int)__fdiv_rn(a.x - xmin, bwx), 0), 9);
            int iy0 = min(max((int)__fdiv_rn(b.x - ymin, bwy), 0), 9);
            int ix1 = min(max((int)__fdiv_rn(a.y - xmin, bwx), 0), 9);
            int iy1 = min(max((int)__fdiv_rn(b.y - ymin, bwy), 0), 9);
            atomicAdd(&hist[ix0 * 10 + iy0], 1u);
            atomicAdd(&hist[ix1 * 10 + iy1], 1u);
        }
        fft16<0>(x);
        #pragma unroll
        for (int q = 0; q < 4; q++){
            ((float4*)(Cr + 16*j))[q] = make_float4(x[4*q].x, x[4*q+1].x, x[4*q+2].x, x[4*q+3].x);
            ((float4*)(Ci + 16*j))[q] = make_float4(x[4*q].y, x[4*q+1].y, x[4*q+2].y, x[4*q+3].y);
        }
    }
    __syncthreads();

    // ---- MI final math on warp 0 (hist is stable from here on) ----
    if (warp == 0){
        const float eps = 1e-8f;
        const float invD = 1.0f / 8388608.0f;   // 1/(B*S), faithful to reference
        if (lane < 10){
            float hx = 0.f, hy = 0.f;
            for (int j = 0; j < 10; j++){
                hx += (float)hist[lane*10 + j];
                hy += (float)hist[j*10 + lane];
            }
            s_hx[lane] = hx; s_hy[lane] = hy;
        }
        __syncwarp();
        float mi = 0.f;
        for (int b = lane; b < 100; b += 32){
            float px  = s_hx[b/10] * invD;
            float py  = s_hy[b%10] * invD;
            float pxy = (float)hist[b] * invD;
            mi += pxy * logf(__fdiv_rn(pxy + eps, px * py + eps));
        }
        mi = warp_sum(mi);
        float he = 0.f;
        if (lane < 10){
            float px = s_hx[lane] * invD, py = s_hy[lane] * invD;
            he = -px * logf(px + eps) - py * logf(py + eps);
        }
        he = warp_sum(he);
        if (lane == 0) atomicAdd(&g_nmi, (double)(mi / (0.5f * he)));
    }

    pass4<4,0>(Cr, Ci, Ar, Ai, Wt);  __syncthreads();
    pass4<6,0>(Ar, Ai, Cr, Ci, Wt);  __syncthreads();
    pass4<8,0>(Cr, Ci, Ar, Ai, Wt);  __syncthreads();
    pass4<10,0>(Ar, Ai, Cr, Ci, Wt); __syncthreads();
    pass2<0>(Cr, Ci, Ar, Ai, Wt);    __syncthreads();   // pred spectrum in A

    // ---- forward FFT chain (targ): B <-> C ----
    pass16<0>(Br, Bi, Cr, Ci);       __syncthreads();
    pass4<4,0>(Cr, Ci, Br, Bi, Wt);  __syncthreads();
    pass4<6,0>(Br, Bi, Cr, Ci, Wt);  __syncthreads();
    pass4<8,0>(Cr, Ci, Br, Bi, Wt);  __syncthreads();
    pass4<10,0>(Br, Bi, Cr, Ci, Wt); __syncthreads();
    pass2<0>(Cr, Ci, Br, Bi, Wt);    __syncthreads();   // targ spectrum in B

    // ---- spectra: power-spectrum sums + hann-windowed phase correlation -> C ----
    float accd = 0.f, acct = 0.f;
    float2 lastX0p, lastX0t, lastXpp, lastXpt;
    for (int it = 0; it < 16; it++){
        int k = tid + it * 512;               // 0..8191
        float2 w0 = g_WN[k];
        float2 X0p = spec_at(Ar, Ai, k, w0);
        float2 X0t = spec_at(Br, Bi, k, w0);
        float2 Xmp, Xmt, Xpp, Xpt;
        Xmp.x = __shfl_up_sync(0xffffffffu, X0p.x, 1);
        Xmp.y = __shfl_up_sync(0xffffffffu, X0p.y, 1);
        Xmt.x = __shfl_up_sync(0xffffffffu, X0t.x, 1);
        Xmt.y = __shfl_up_sync(0xffffffffu, X0t.y, 1);
        Xpp.x = __shfl_down_sync(0xffffffffu, X0p.x, 1);
        Xpp.y = __shfl_down_sync(0xffffffffu, X0p.y, 1);
        Xpt.x = __shfl_down_sync(0xffffffffu, X0t.x, 1);
        Xpt.y = __shfl_down_sync(0xffffffffu, X0t.y, 1);
        if (lane == 0){
            if (k == 0){
                float2 w1 = g_WN[1];
                Xmp = cconj(spec_at(Ar, Ai, 1, w1));   // X[-1] = conj(X[1])
                Xmt = cconj(spec_at(Br, Bi, 1, w1));
            } else {
                float2 wm = g_WN[k-1];
                Xmp = spec_at(Ar, Ai, k-1, wm);
                Xmt = spec_at(Br, Bi, k-1, wm);
            }
        }
        if (lane == 31){
            float2 wp = g_WN[k+1];
            Xpp = spec_at(Ar, Ai, k+1, wp);
            Xpt = spec_at(Br, Bi, k+1, wp);
        }
        float pp = X0p.x*X0p.x + X0p.y*X0p.y;
        float pt = X0t.x*X0t.x + X0t.y*X0t.y;
        accd += fabsf(pp - pt);
        acct += pt;
        float2 xf = make_float2(0.5f*X0p.x - 0.25f*(Xmp.x + Xpp.x),
                                0.5f*X0p.y - 0.25f*(Xmp.y + Xpp.y));
        float2 tf = make_float2(0.5f*X0t.x - 0.25f*(Xmt.x + Xpt.x),
                                0.5f*X0t.y - 0.25f*(Xmt.y + Xpt.y));
        float2 c = cmul(xf, cconj(tf));
        float inv = rsqrtf(c.x*c.x + c.y*c.y);
        Cr[k] = c.x * inv; Ci[k] = c.y * inv;
        lastX0p = X0p; lastX0t = X0t; lastXpp = Xpp; lastXpt = Xpt;
    }
    if (tid == THREADS - 1){
        // bin 8192: X0' = X[8192] (= lastXpp), Xm' = X[8191], Xp' = conj(X[8191])
        float2 X0p = lastXpp, X0t = lastXpt;
        float2 Xmp = lastX0p, Xmt = lastX0t;
        float2 Xpp = cconj(Xmp), Xpt = cconj(Xmt);
        float pp = X0p.x*X0p.x + X0p.y*X0p.y;
        float pt = X0t.x*X0t.x + X0t.y*X0t.y;
        accd += fabsf(pp - pt);
        acct += pt;
        float2 xf = make_float2(0.5f*X0p.x - 0.25f*(Xmp.x + Xpp.x),
                                0.5f*X0p.y - 0.25f*(Xmp.y + Xpp.y));
        float2 tf = make_float2(0.5f*X0t.x - 0.25f*(Xmt.x + Xpt.x),
                                0.5f*X0t.y - 0.25f*(Xmt.y + Xpt.y));
        float2 c = cmul(xf, cconj(tf));
        float inv = rsqrtf(c.x*c.x + c.y*c.y);
        s_c8192 = make_float2(c.x * inv, c.y * inv);
    }
    accd = warp_sum(accd); acct = warp_sum(acct);
    if (lane == 0){ s_red[warp][0] = accd; s_red[warp][1] = acct; }
    __syncthreads();
    if (tid == 0){
        double d = 0.0, t2 = 0.0;
        for (int w = 0; w < 16; w++){ d += s_red[w][0]; t2 += s_red[w][1]; }
        atomicAdd(&g_absdiff, d);
        atomicAdd(&g_tp, t2);
    }

    // ---- pack spectrum for real inverse FFT: C -> A (natural order) ----
    #pragma unroll 4
    for (int it = 0; it < 16; it++){
        int k = tid + it * 512;
        float2 Ck = make_float2(Cr[k], Ci[k]);
        float2 Ck2 = (k == 0) ? s_c8192
                              : make_float2(Cr[8192 - k], -Ci[8192 - k]);  // conj(C[8192-k])
        float2 E = make_float2(0.5f*(Ck.x + Ck2.x), 0.5f*(Ck.y + Ck2.y));
        float2 D = make_float2(0.5f*(Ck.x - Ck2.x), 0.5f*(Ck.y - Ck2.y));
        float2 wn = cconj(g_WN[k]);              // e^{+i pi k/8192}
        float2 O  = cmul(wn, D);
        Ar[k] = E.x - O.y; Ai[k] = E.y + O.x;    // E + i*O
    }
    __syncthreads();

    // ---- inverse FFT chain: A <-> C ----
    pass16<1>(Ar, Ai, Cr, Ci);       __syncthreads();
    pass4<4,1>(Cr, Ci, Ar, Ai, Wt);  __syncthreads();
    pass4<6,1>(Ar, Ai, Cr, Ci, Wt);  __syncthreads();
    pass4<8,1>(Cr, Ci, Ar, Ai, Wt);  __syncthreads();
    pass4<10,1>(Ar, Ai, Cr, Ci, Wt); __syncthreads();
    pass2<1>(Cr, Ci, Ar, Ai, Wt);    __syncthreads();   // time-domain in A

    // ---- argmax over 16384 real samples (first-occurrence tie break) ----
    float best = -INFINITY; int bi = 0x7fffffff;
    #pragma unroll 4
    for (int it = 0; it < 16; it++){
        int n = tid + it * 512;
        float ze = Ar[n], zo = Ai[n];     // y[2n], y[2n+1]
        int e = 2*n, o = 2*n + 1;
        if (ze > best || (ze == best && e < bi)){ best = ze; bi = e; }
        if (zo > best || (zo == best && o < bi)){ best = zo; bi = o; }
    }
    #pragma unroll
    for (int off = 16; off; off >>= 1){
        float ov = __shfl_down_sync(0xffffffffu, best, off);
        int   oi = __shfl_down_sync(0xffffffffu, bi,   off);
        if (ov > best || (ov == best && oi < bi)){ best = ov; bi = oi; }
    }
    if (lane == 0){ s_red[warp][0] = best; s_idx[warp] = bi; }
    __syncthreads();
    if (tid == 0){
        best = s_red[0][0]; bi = s_idx[0];
        for (int w = 1; w < 16; w++){
            float v = s_red[w][0]; int ix = s_idx[w];
            if (v > best || (v == best && ix < bi)){ best = v; bi = ix; }
        }
        atomicAdd(&g_cos, (double)cosf(2.0f * (float)PI_D * (float)bi / 16384.0f));
    }
}

// ---------------- finalize ----------------
__global__ void finalize_kernel(const int* __restrict__ pep, float* __restrict__ out){
    double loss = g_pear / (double)ROWS;
    int ep = *pep;
    if (ep >= 400){
        loss += 1.0 - g_cos / (double)ROWS;     // phase correlation
        loss += g_absdiff / g_tp;               // power spectrum
    }
    if (ep >= 700){
        loss += 1.0 - g_nmi / (double)ROWS;     // mutual information
    }
    out[0] = (float)loss;
}

// ---------------- launch ----------------
extern "C" void kernel_launch(void* const* d_in, const int* in_sizes, int n_in,
                              void* d_out, int out_size){
    const float* pred = (const float*)d_in[0];
    const float* targ = (const float*)d_in[1];
    const int*   pi   = (const int*)d_in[2];
    const int*   pep  = (const int*)d_in[3];
    float* out = (float*)d_out;

    const size_t smem_bytes = (size_t)(6 * 8192) * sizeof(float) + 2048 * sizeof(float2); // 212992
    cudaFuncSetAttribute(row_kernel, cudaFuncAttributeMaxDynamicSharedMemorySize,
                         (int)smem_bytes);

    init_tw_kernel<<<17, 512>>>();
    row_kernel<<<ROWS, THREADS, smem_bytes>>>(pred, targ, pi);
    finalize_kernel<<<1, 1>>>(pep, out);
}

// round 8
// speedup vs baseline: 4.4349x; 1.1859x over previous
#include <cuda_runtime.h>
#include <math.h>
#include <stdint.h>

#define THREADS 512
#define M 8192            // packed complex FFT size
#define NFULL 16384       // real signal length
#define ROWS 512
#define PI_D 3.14159265358979323846

// ---------------- per-row outputs + completion counter (no allocation) --------
struct RowOut { double pear, cosv, absd, tp, nmi; };
__device__ RowOut  g_row[ROWS];
__device__ unsigned g_done = 0;    // monotonic across launches; (prev % ROWS) picks finalizer

// ---------------- complex helpers ----------------
__device__ __forceinline__ float2 cmul(float2 a, float2 b){
    return make_float2(a.x*b.x - a.y*b.y, a.x*b.y + a.y*b.x);
}
__device__ __forceinline__ float2 cadd(float2 a, float2 b){ return make_float2(a.x+b.x, a.y+b.y); }
__device__ __forceinline__ float2 csub(float2 a, float2 b){ return make_float2(a.x-b.x, a.y-b.y); }
__device__ __forceinline__ float2 cconj(float2 a){ return make_float2(a.x, -a.y); }

__device__ __forceinline__ float warp_sum(float v){
    #pragma unroll
    for (int o = 16; o; o >>= 1) v += __shfl_down_sync(0xffffffffu, v, o);
    return v;
}
__device__ __forceinline__ double warp_sum_d(double v){
    #pragma unroll
    for (int o = 16; o; o >>= 1) v += __shfl_down_sync(0xffffffffu, v, o);
    return v;
}

// e^{-i pi f} (forward) / e^{+i pi f} (inverse)
template<int INV>
__device__ __forceinline__ float2 eip(float f){
    float s, c;
    sincospif(INV ? f : -f, &s, &c);
    return make_float2(c, s);
}

template<int INV>
__device__ __forceinline__ float2 cmulK(float2 a, float wr, float wi){
    float i2 = INV ? -wi : wi;
    return make_float2(a.x*wr - a.y*i2, a.x*i2 + a.y*wr);
}

// radix-4 DIT butterfly
template<int INV>
__device__ __forceinline__ void bfly4(float2 b0, float2 b1, float2 b2, float2 b3,
                                      float2& o0, float2& o1, float2& o2, float2& o3){
    float2 s  = cadd(b0, b2), d  = csub(b0, b2);
    float2 s2 = cadd(b1, b3), d2 = csub(b1, b3);
    o0 = cadd(s, s2); o2 = csub(s, s2);
    if (!INV){ o1 = make_float2(d.x + d2.y, d.y - d2.x); o3 = make_float2(d.x - d2.y, d.y + d2.x); }
    else     { o1 = make_float2(d.x - d2.y, d.y + d2.x); o3 = make_float2(d.x + d2.y, d.y - d2.x); }
}

// 16-point FFT in registers, natural in/out (two radix-4 micro-passes)
template<int INV>
__device__ __forceinline__ void fft16(float2* x){
    float2 t[16];
    #pragma unroll
    for (int g = 0; g < 4; g++)
        bfly4<INV>(x[g], x[g+4], x[g+8], x[g+12], t[4*g], t[4*g+1], t[4*g+2], t[4*g+3]);
    const float C1 = 0.9238795325112867f, S1 = 0.3826834323650898f, R2 = 0.7071067811865476f;
    bfly4<INV>(t[0], t[4], t[8], t[12], x[0], x[4], x[8], x[12]);
    bfly4<INV>(t[1], cmulK<INV>(t[5],  C1, -S1), cmulK<INV>(t[9],  R2, -R2), cmulK<INV>(t[13],  S1, -C1),
               x[1], x[5], x[9], x[13]);
    bfly4<INV>(t[2], cmulK<INV>(t[6],  R2, -R2), cmulK<INV>(t[10], 0.f, -1.f), cmulK<INV>(t[14], -R2, -R2),
               x[2], x[6], x[10], x[14]);
    bfly4<INV>(t[3], cmulK<INV>(t[7],  S1, -C1), cmulK<INV>(t[11], -R2, -R2), cmulK<INV>(t[15], -C1,  S1),
               x[3], x[7], x[11], x[15]);
}

// Stockham radix-16 pass, L=1 (twiddle-free): in[j+512c] -> out[16j+c]
template<int INV>
__device__ __forceinline__ void pass16(const float* __restrict__ ri, const float* __restrict__ ii,
                                       float* __restrict__ ro, float* __restrict__ io){
    int j = threadIdx.x;
    float2 x[16];
    #pragma unroll
    for (int c = 0; c < 16; c++){ x[c].x = ri[j + 512*c]; x[c].y = ii[j + 512*c]; }
    fft16<INV>(x);
    #pragma unroll
    for (int q = 0; q < 4; q++){
        ((float4*)(ro + 16*j))[q] = make_float4(x[4*q].x, x[4*q+1].x, x[4*q+2].x, x[4*q+3].x);
        ((float4*)(io + 16*j))[q] = make_float4(x[4*q].y, x[4*q+1].y, x[4*q+2].y, x[4*q+3].y);
    }
}

// Stockham radix-16 pass at sub-length L = 2^LOG2L (L in {16, 256}).
// out[r + L(16s + c)] = sum_m in[r + Ls + 512 m] * W_{16L}^{rm} * W_16^{cm}
template<int LOG2L, int INV>
__device__ __forceinline__ void passR16(const float* __restrict__ ri, const float* __restrict__ ii,
                                        float* __restrict__ ro, float* __restrict__ io){
    const int L = 1 << LOG2L;
    int j = threadIdx.x;                 // j = L*s + r, 0..511
    int r = j & (L - 1);
    int s = j >> LOG2L;
    float2 x[16];
    #pragma unroll
    for (int m = 0; m < 16; m++){ x[m].x = ri[j + 512*m]; x[m].y = ii[j + 512*m]; }
    // twiddles: w1 = e^{-2 pi i r / (16 L)} = e^{-i pi r/(8L)}, chained powers
    float2 w1 = eip<INV>((float)r * (1.0f / (8.0f * (float)L)));
    float2 wm = w1;
    #pragma unroll
    for (int m = 1; m < 16; m++){
        x[m] = cmul(x[m], wm);
        wm = cmul(wm, w1);
    }
    fft16<INV>(x);
    int base = r + (s << (LOG2L + 4));
    #pragma unroll
    for (int c = 0; c < 16; c++){
        ro[base + (c << LOG2L)] = x[c].x;
        io[base + (c << LOG2L)] = x[c].y;
    }
}

// final Stockham radix-2 pass (L=4096)
template<int INV>
__device__ __forceinline__ void pass2(const float* __restrict__ ri, const float* __restrict__ ii,
                                      float* __restrict__ ro, float* __restrict__ io){
    #pragma unroll
    for (int it = 0; it < 8; it++){
        int j = threadIdx.x + it * 512;
        float2 a = make_float2(ri[j], ii[j]);
        float2 b = make_float2(ri[j + 4096], ii[j + 4096]);
        float2 v = cmul(b, eip<INV>((float)j * (1.0f / 4096.0f)));
        ro[j] = a.x + v.x;        io[j] = a.y + v.y;
        ro[j + 4096] = a.x - v.x; io[j + 4096] = a.y - v.y;
    }
}

// unpack X[k] of the length-16384 real signal from packed spectrum planes
__device__ __forceinline__ float2 spec_at(const float* __restrict__ re, const float* __restrict__ im,
                                          int k, float2 w){
    int k1 = k & (M - 1), k2 = (M - k) & (M - 1);
    float2 a = make_float2(re[k1], im[k1]);
    float2 b = make_float2(re[k2], im[k2]);
    float2 E = make_float2(0.5f*(a.x + b.x),  0.5f*(a.y - b.y));
    float2 O = make_float2(0.5f*(a.y + b.y), -0.5f*(a.x - b.x));
    float2 WO = cmul(w, O);
    return make_float2(E.x + WO.x, E.y + WO.y);
}

// ---------------- single fused kernel: one CTA per row, last CTA finalizes ----
__global__ __launch_bounds__(THREADS, 1)
void row_kernel(const float* __restrict__ pred, const float* __restrict__ targ,
                const int* __restrict__ pi, const int* __restrict__ pep,
                float* __restrict__ out){
    extern __shared__ float smf[];
    float* Ar = smf;
    float* Ai = smf + 8192;
    float* Br = smf + 16384;
    float* Bi = smf + 24576;
    float* Cr = smf + 32768;
    float* Ci = smf + 40960;

    __shared__ float    s_red[16][10];
    __shared__ int      s_idx[16];
    __shared__ float    s_mm[4];
    __shared__ unsigned hist[100];
    __shared__ float    s_hx[10], s_hy[10];
    __shared__ float2   s_c8192;
    __shared__ unsigned s_last;
    __shared__ double   s_fin[16][5];

    const int tid  = threadIdx.x;
    const int warp = tid >> 5, lane = tid & 31;
    const int row  = blockIdx.x;
    const int i0   = *pi;

    // tid0-resident per-row results
    double r_pear = 0.0, r_cos = 0.0, r_absd = 0.0, r_tp = 0.0, r_nmi = 0.0;

    const float2* xr = (const float2*)(pred + ((size_t)i0 * ROWS + row) * (size_t)NFULL);
    const float2* yr = (const float2*)(targ + (size_t)row * (size_t)NFULL);

    if (tid < 100) hist[tid] = 0u;

    // ---- load (SoA natural order) + Pearson moments + min/max ----
    float sx = 0.f, sy = 0.f, sxy = 0.f, sx2 = 0.f, sy2 = 0.f;
    float xmn = INFINITY, xmx = -INFINITY, ymn = INFINITY, ymx = -INFINITY;
    #pragma unroll 4
    for (int it = 0; it < 16; it++){
        int n = tid + it * THREADS;
        float2 a = xr[n], b = yr[n];
        sx  += a.x + a.y;          sy  += b.x + b.y;
        sxy += a.x*b.x + a.y*b.y;
        sx2 += a.x*a.x + a.y*a.y;  sy2 += b.x*b.x + b.y*b.y;
        xmn = fminf(xmn, fminf(a.x, a.y)); xmx = fmaxf(xmx, fmaxf(a.x, a.y));
        ymn = fminf(ymn, fminf(b.x, b.y)); ymx = fmaxf(ymx, fmaxf(b.x, b.y));
        Ar[n] = a.x; Ai[n] = a.y;
        Br[n] = b.x; Bi[n] = b.y;
    }
    sx  = warp_sum(sx);  sy  = warp_sum(sy); sxy = warp_sum(sxy);
    sx2 = warp_sum(sx2); sy2 = warp_sum(sy2);
    #pragma unroll
    for (int o = 16; o; o >>= 1){
        xmn = fminf(xmn, __shfl_down_sync(0xffffffffu, xmn, o));
        xmx = fmaxf(xmx, __shfl_down_sync(0xffffffffu, xmx, o));
        ymn = fminf(ymn, __shfl_down_sync(0xffffffffu, ymn, o));
        ymx = fmaxf(ymx, __shfl_down_sync(0xffffffffu, ymx, o));
    }
    if (lane == 0){
        s_red[warp][0]=sx;  s_red[warp][1]=sy;  s_red[warp][2]=sxy;
        s_red[warp][3]=sx2; s_red[warp][4]=sy2;
        s_red[warp][5]=xmn; s_red[warp][6]=xmx; s_red[warp][7]=ymn; s_red[warp][8]=ymx;
    }
    __syncthreads();
    if (tid == 0){
        double Sx=0,Sy=0,Sxy=0,Sx2=0,Sy2=0;
        float a = s_red[0][5], b = s_red[0][6], c = s_red[0][7], d = s_red[0][8];
        for (int w = 0; w < 16; w++){
            Sx+=s_red[w][0]; Sy+=s_red[w][1]; Sxy+=s_red[w][2];
            Sx2+=s_red[w][3]; Sy2+=s_red[w][4];
            a = fminf(a, s_red[w][5]); b = fmaxf(b, s_red[w][6]);
            c = fminf(c, s_red[w][7]); d = fmaxf(d, s_red[w][8]);
        }
        const double N = (double)NFULL;
        r_pear = 1.0 - (N*Sxy - Sx*Sy) / sqrt((N*Sx2 - Sx*Sx) * (N*Sy2 - Sy*Sy));
        s_mm[0]=a; s_mm[1]=b; s_mm[2]=c; s_mm[3]=d;
    }
    __syncthreads();

    // ---- pred FFT pass 1 (A -> C) with MI histogram fused ----
    {
        const float xmin = s_mm[0], ymin = s_mm[2];
        const float bwx = __fdiv_rn(s_mm[1] - s_mm[0], 10.0f);
        const float bwy = __fdiv_rn(s_mm[3] - s_mm[2], 10.0f);
        int j = tid;
        float2 x[16];
        #pragma unroll
        for (int c = 0; c < 16; c++){
            int n = j + 512*c;
            float2 a = make_float2(Ar[n], Ai[n]);
            float2 b = make_float2(Br[n], Bi[n]);
            x[c] = a;
            int ix0 = min(max((int)__fdiv_rn(a.x - xmin, bwx), 0), 9);
            int iy0 = min(max((int)__fdiv_rn(b.x - ymin, bwy), 0), 9);
            int ix1 = min(max((int)__fdiv_rn(a.y - xmin, bwx), 0), 9);
            int iy1 = min(max((int)__fdiv_rn(b.y - ymin, bwy), 0), 9);
            atomicAdd(&hist[ix0 * 10 + iy0], 1u);
            atomicAdd(&hist[ix1 * 10 + iy1], 1u);
        }
        fft16<0>(x);
        #pragma unroll
        for (int q = 0; q < 4; q++){
            ((float4*)(Cr + 16*j))[q] = make_float4(x[4*q].x, x[4*q+1].x, x[4*q+2].x, x[4*q+3].x);
            ((float4*)(Ci + 16*j))[q] = make_float4(x[4*q].y, x[4*q+1].y, x[4*q+2].y, x[4*q+3].y);
        }
    }
    __syncthreads();

    // ---- MI final math on warp 0 (hist stable; other warps proceed) ----
    if (warp == 0){
        const float eps = 1e-8f;
        const float invD = 1.0f / 8388608.0f;   // 1/(B*S), faithful to reference
        if (lane < 10){
            float hx = 0.f, hy = 0.f;
            for (int j = 0; j < 10; j++){
                hx += (float)hist[lane*10 + j];
                hy += (float)hist[j*10 + lane];
            }
            s_hx[lane] = hx; s_hy[lane] = hy;
        }
        __syncwarp();
        float mi = 0.f;
        for (int b = lane; b < 100; b += 32){
            float px  = s_hx[b/10] * invD;
            float py  = s_hy[b%10] * invD;
            float pxy = (float)hist[b] * invD;
            mi += pxy * logf(__fdiv_rn(pxy + eps, px * py + eps));
        }
        mi = warp_sum(mi);
        float he = 0.f;
        if (lane < 10){
            float px = s_hx[lane] * invD, py = s_hy[lane] * invD;
            he = -px * logf(px + eps) - py * logf(py + eps);
        }
        he = warp_sum(he);
        if (lane == 0) r_nmi = (double)(mi / (0.5f * he));
    }

    passR16<4,0>(Cr, Ci, Ar, Ai); __syncthreads();
    passR16<8,0>(Ar, Ai, Cr, Ci); __syncthreads();
    pass2<0>(Cr, Ci, Ar, Ai);     __syncthreads();   // pred spectrum in A

    // ---- targ forward FFT: B <-> C ----
    pass16<0>(Br, Bi, Cr, Ci);    __syncthreads();
    passR16<4,0>(Cr, Ci, Br, Bi); __syncthreads();
    passR16<8,0>(Br, Bi, Cr, Ci); __syncthreads();
    pass2<0>(Cr, Ci, Br, Bi);     __syncthreads();   // targ spectrum in B

    // ---- spectra: power-spectrum sums + hann-windowed phase correlation -> C ----
    float accd = 0.f, acct = 0.f;
    float2 lastX0p, lastX0t, lastXpp, lastXpt;
    for (int it = 0; it < 16; it++){
        int k = tid + it * 512;               // 0..8191
        float2 w0 = eip<0>((float)k * (1.0f/8192.0f));
        float2 X0p = spec_at(Ar, Ai, k, w0);
        float2 X0t = spec_at(Br, Bi, k, w0);
        float2 Xmp, Xmt, Xpp, Xpt;
        Xmp.x = __shfl_up_sync(0xffffffffu, X0p.x, 1);
        Xmp.y = __shfl_up_sync(0xffffffffu, X0p.y, 1);
        Xmt.x = __shfl_up_sync(0xffffffffu, X0t.x, 1);
        Xmt.y = __shfl_up_sync(0xffffffffu, X0t.y, 1);
        Xpp.x = __shfl_down_sync(0xffffffffu, X0p.x, 1);
        Xpp.y = __shfl_down_sync(0xffffffffu, X0p.y, 1);
        Xpt.x = __shfl_down_sync(0xffffffffu, X0t.x, 1);
        Xpt.y = __shfl_down_sync(0xffffffffu, X0t.y, 1);
        if (lane == 0){
            if (k == 0){
                float2 w1 = eip<0>(1.0f/8192.0f);
                Xmp = cconj(spec_at(Ar, Ai, 1, w1));   // X[-1] = conj(X[1])
                Xmt = cconj(spec_at(Br, Bi, 1, w1));
            } else {
                float2 wm = eip<0>((float)(k-1) * (1.0f/8192.0f));
                Xmp = spec_at(Ar, Ai, k-1, wm);
                Xmt = spec_at(Br, Bi, k-1, wm);
            }
        }
        if (lane == 31){
            float2 wp = eip<0>((float)(k+1) * (1.0f/8192.0f));
            Xpp = spec_at(Ar, Ai, k+1, wp);
            Xpt = spec_at(Br, Bi, k+1, wp);
        }
        float pp = X0p.x*X0p.x + X0p.y*X0p.y;
        float pt = X0t.x*X0t.x + X0t.y*X0t.y;
        accd += fabsf(pp - pt);
        acct += pt;
        float2 xf = make_float2(0.5f*X0p.x - 0.25f*(Xmp.x + Xpp.x),
                                0.5f*X0p.y - 0.25f*(Xmp.y + Xpp.y));
        float2 tf = make_float2(0.5f*X0t.x - 0.25f*(Xmt.x + Xpt.x),
                                0.5f*X0t.y - 0.25f*(Xmt.y + Xpt.y));
        float2 c = cmul(xf, cconj(tf));
        float inv = rsqrtf(c.x*c.x + c.y*c.y);
        Cr[k] = c.x * inv; Ci[k] = c.y * inv;
        lastX0p = X0p; lastX0t = X0t; lastXpp = Xpp; lastXpt = Xpt;
    }
    if (tid == THREADS - 1){
        // bin 8192: X0' = X[8192] (= lastXpp), Xm' = X[8191], Xp' = conj(X[8191])
        float2 X0p = lastXpp, X0t = lastXpt;
        float2 Xmp = lastX0p, Xmt = lastX0t;
        float2 Xpp = cconj(Xmp), Xpt = cconj(Xmt);
        float pp = X0p.x*X0p.x + X0p.y*X0p.y;
        float pt = X0t.x*X0t.x + X0t.y*X0t.y;
        accd += fabsf(pp - pt);
        acct += pt;
        float2 xf = make_float2(0.5f*X0p.x - 0.25f*(Xmp.x + Xpp.x),
                                0.5f*X0p.y - 0.25f*(Xmp.y + Xpp.y));
        float2 tf = make_float2(0.5f*X0t.x - 0.25f*(Xmt.x + Xpt.x),
                                0.5f*X0t.y - 0.25f*(Xmt.y + Xpt.y));
        float2 c = cmul(xf, cconj(tf));
        float inv = rsqrtf(c.x*c.x + c.y*c.y);
        s_c8192 = make_float2(c.x * inv, c.y * inv);
    }
    accd = warp_sum(accd); acct = warp_sum(acct);
    if (lane == 0){ s_red[warp][0] = accd; s_red[warp][1] = acct; }
    __syncthreads();
    if (tid == 0){
        double d = 0.0, t2 = 0.0;
        for (int w = 0; w < 16; w++){ d += s_red[w][0]; t2 += s_red[w][1]; }
        r_absd = d; r_tp = t2;
    }

    // ---- pack spectrum for real inverse FFT: C -> A (natural order) ----
    #pragma unroll 4
    for (int it = 0; it < 16; it++){
        int k = tid + it * 512;
        float2 Ck = make_float2(Cr[k], Ci[k]);
        float2 Ck2 = (k == 0) ? s_c8192
                              : make_float2(Cr[8192 - k], -Ci[8192 - k]);  // conj(C[8192-k])
        float2 E = make_float2(0.5f*(Ck.x + Ck2.x), 0.5f*(Ck.y + Ck2.y));
        float2 D = make_float2(0.5f*(Ck.x - Ck2.x), 0.5f*(Ck.y - Ck2.y));
        float2 wn = eip<1>((float)k * (1.0f/8192.0f));   // e^{+i pi k/8192}
        float2 O  = cmul(wn, D);
        Ar[k] = E.x - O.y; Ai[k] = E.y + O.x;            // E + i*O
    }
    __syncthreads();

    // ---- inverse FFT chain: A <-> C ----
    pass16<1>(Ar, Ai, Cr, Ci);    __syncthreads();
    passR16<4,1>(Cr, Ci, Ar, Ai); __syncthreads();
    passR16<8,1>(Ar, Ai, Cr, Ci); __syncthreads();
    pass2<1>(Cr, Ci, Ar, Ai);     __syncthreads();   // time-domain in A

    // ---- argmax over 16384 real samples (first-occurrence tie break) ----
    float best = -INFINITY; int bi = 0x7fffffff;
    #pragma unroll 4
    for (int it = 0; it < 16; it++){
        int n = tid + it * 512;
        float ze = Ar[n], zo = Ai[n];     // y[2n], y[2n+1]
        int e = 2*n, o = 2*n + 1;
        if (ze > best || (ze == best && e < bi)){ best = ze; bi = e; }
        if (zo > best || (zo == best && o < bi)){ best = zo; bi = o; }
    }
    #pragma unroll
    for (int off = 16; off; off >>= 1){
        float ov = __shfl_down_sync(0xffffffffu, best, off);
        int   oi = __shfl_down_sync(0xffffffffu, bi,   off);
        if (ov > best || (ov == best && oi < bi)){ best = ov; bi = oi; }
    }
    if (lane == 0){ s_red[warp][0] = best; s_idx[warp] = bi; }
    __syncthreads();
    if (tid == 0){
        best = s_red[0][0]; bi = s_idx[0];
        for (int w = 1; w < 16; w++){
            float v = s_red[w][0]; int ix = s_idx[w];
            if (v > best || (v == best && ix < bi)){ best = v; bi = ix; }
        }
        r_cos = (double)cosf(2.0f * (float)PI_D * (float)bi / 16384.0f);

        // publish this row's results (release), then arrive
        g_row[row].pear = r_pear;
        g_row[row].cosv = r_cos;
        g_row[row].absd = r_absd;
        g_row[row].tp   = r_tp;
        g_row[row].nmi  = r_nmi;
        __threadfence();
        unsigned prev = atomicAdd(&g_done, 1u);
        s_last = ((prev % ROWS) == ROWS - 1) ? 1u : 0u;
        if (s_last) __threadfence();   // acquire: order g_row reads after counter observation
    }
    __syncthreads();

    // ---- last CTA reduces all rows and writes the scalar loss ----
    if (s_last){
        double pe = 0.0, co = 0.0, ad = 0.0, tp = 0.0, nm = 0.0;
        for (int r = tid; r < ROWS; r += THREADS){
            const double* p = (const double*)&g_row[r];
            pe += __ldcg(p + 0);
            co += __ldcg(p + 1);
            ad += __ldcg(p + 2);
            tp += __ldcg(p + 3);
            nm += __ldcg(p + 4);
        }
        pe = warp_sum_d(pe); co = warp_sum_d(co); ad = warp_sum_d(ad);
        tp = warp_sum_d(tp); nm = warp_sum_d(nm);
        if (lane == 0){
            s_fin[warp][0]=pe; s_fin[warp][1]=co; s_fin[warp][2]=ad;
            s_fin[warp][3]=tp; s_fin[warp][4]=nm;
        }
        __syncthreads();
        if (tid == 0){
            double Pe=0, Co=0, Ad=0, Tp=0, Nm=0;
            for (int w = 0; w < 16; w++){
                Pe+=s_fin[w][0]; Co+=s_fin[w][1]; Ad+=s_fin[w][2];
                Tp+=s_fin[w][3]; Nm+=s_fin[w][4];
            }
            int ep = *pep;
            double loss = Pe / (double)ROWS;
            if (ep >= 400){
                loss += 1.0 - Co / (double)ROWS;   // phase correlation
                loss += Ad / Tp;                   // power spectrum
            }
            if (ep >= 700){
                loss += 1.0 - Nm / (double)ROWS;   // mutual information
            }
            out[0] = (float)loss;
        }
    }
}

// ---------------- launch ----------------
extern "C" void kernel_launch(void* const* d_in, const int* in_sizes, int n_in,
                              void* d_out, int out_size){
    const float* pred = (const float*)d_in[0];
    const float* targ = (const float*)d_in[1];
    const int*   pi   = (const int*)d_in[2];
    const int*   pep  = (const int*)d_in[3];
    float* out = (float*)d_out;

    const size_t smem_bytes = (size_t)(6 * 8192) * sizeof(float);  // 196608
    cudaFuncSetAttribute(row_kernel, cudaFuncAttributeMaxDynamicSharedMemorySize,
                         (int)smem_bytes);

    row_kernel<<<ROWS, THREADS, smem_bytes>>>(pred, targ, pi, pep, out);
}